// round 1
// baseline (speedup 1.0000x reference)
#include <cuda_runtime.h>
#include <math.h>

// ---------------------------------------------------------------------------
// BSLoss: PINN loss for Black-Scholes on a 4096x4096 (S x t) grid.
//   total = pde_sum/n_int + 10*bc_sum/N_T + 10*tc_sum/N_S
// Layout: V[s][j], j (time) contiguous, row stride 4096 floats.
// ---------------------------------------------------------------------------

#define NS 4096
#define NT 4096
#define ROWF 4096

// Accumulators: [0]=pde, [1]=bc(Smax row), [2]=terminal(huber)
__device__ double g_acc[3];

__global__ void k_zero() {
    g_acc[0] = 0.0; g_acc[1] = 0.0; g_acc[2] = 0.0;
}

// f32 constants (derived from double on host side conceptually; exact enough)
#define INV4095   (1.0f / 4095.0f)
#define INV2DU    2047.5f                 // 1/(2*DU), DU = 1/4095  (exact)
#define INVDU2    16769025.0f             // 4095^2, exact in f32
#define INV2DT    102375.0f               // 1/(2*DT_NORM) = 4095/0.04
#define ALPHA_C   2.5f                    // 2r/sigma^2
#define STRIP     16

__device__ __forceinline__ float pde_comp(float vm, float vc, float vp,
                                          float vtl, float vtr,
                                          float Sn, float Sun, float Suun,
                                          float invSun, float invSun3,
                                          float Sn2, float aSn) {
    float V_u  = (vp - vm) * INV2DU;
    float V_uu = (vp + vm - 2.0f * vc) * INVDU2;
    float V_t  = (vtr - vtl) * INV2DT;
    float V_S  = V_u * invSun;
    float V_SS = (V_uu * Sun - V_u * Suun) * invSun3;
    V_SS = fminf(100.0f, fmaxf(-100.0f, V_SS));
    float r = V_t - Sn2 * V_SS - aSn * V_S + ALPHA_C * vc;
    return r * r;
}

__global__ void __launch_bounds__(256, 8)
k_pde(const float* __restrict__ V, float C1f, float C2f) {
    const int tid  = threadIdx.x;
    const int lane = tid & 31;
    const int wid  = tid >> 5;

    const int j4 = (blockIdx.x * 256 + tid) * 4;     // grid.x = 4  -> j4 in [0,4096)
    const int s0 = 1 + blockIdx.y * STRIP;           // grid.y = 256 -> s in [1,4096)
    const int send = min(s0 + STRIP, NS - 1);        // s <= 4094

    // interior-column masks for the 4 lanes of the float4
    float mk0 = (j4 + 0 >= 1 && j4 + 0 <= NT - 2) ? 1.0f : 0.0f;
    float mk1 = (j4 + 1 >= 1 && j4 + 1 <= NT - 2) ? 1.0f : 0.0f;
    float mk2 = (j4 + 2 >= 1 && j4 + 2 <= NT - 2) ? 1.0f : 0.0f;
    float mk3 = (j4 + 3 >= 1 && j4 + 3 <= NT - 2) ? 1.0f : 0.0f;

    const float dL = C2f - C1f;
    const float* col = V + j4;

    float4 m = *reinterpret_cast<const float4*>(col + (size_t)(s0 - 1) * ROWF);
    float4 c = *reinterpret_cast<const float4*>(col + (size_t)s0 * ROWF);

    float facc = 0.0f;

    for (int s = s0; s < send; ++s) {
        float4 p = *reinterpret_cast<const float4*>(col + (size_t)(s + 1) * ROWF);

        // j-1 / j+4 halo via warp shuffle; edge lanes load (predicated)
        float l = __shfl_up_sync(0xffffffffu, c.w, 1);
        float r = __shfl_down_sync(0xffffffffu, c.x, 1);
        if (lane == 0)  l = (j4 > 0)        ? col[(size_t)s * ROWF - 1] : 0.0f;
        if (lane == 31) r = (j4 + 4 < NT)   ? col[(size_t)s * ROWF + 4] : 0.0f;

        // per-row stretch metrics (warp-uniform)
        float u    = (float)s * INV4095;
        float L    = fmaf(dL, u, C1f);
        float S    = fmaf(30.0f, fmaf(L * L * L, (1.0f / 6.0f), L), 100.0f);
        float dS   = 30.0f * dL * fmaf(0.5f, L * L, 1.0f);
        float d2S  = 30.0f * dL * dL * L;
        float Sn   = S   * (1.0f / 300.0f);
        float Sun  = dS  * (1.0f / 300.0f);
        float Suun = d2S * (1.0f / 300.0f);
        float invSun  = 1.0f / Sun;
        float invSun3 = invSun * invSun * invSun;
        float Sn2 = Sn * Sn;
        float aSn = ALPHA_C * Sn;

        facc += mk0 * pde_comp(m.x, c.x, p.x, l,   c.y, Sn, Sun, Suun, invSun, invSun3, Sn2, aSn);
        facc += mk1 * pde_comp(m.y, c.y, p.y, c.x, c.z, Sn, Sun, Suun, invSun, invSun3, Sn2, aSn);
        facc += mk2 * pde_comp(m.z, c.z, p.z, c.y, c.w, Sn, Sun, Suun, invSun, invSun3, Sn2, aSn);
        facc += mk3 * pde_comp(m.w, c.w, p.w, c.z, r,   Sn, Sun, Suun, invSun, invSun3, Sn2, aSn);

        m = c; c = p;
    }

    // block reduce -> one double atomic per block
    #pragma unroll
    for (int o = 16; o; o >>= 1) facc += __shfl_xor_sync(0xffffffffu, facc, o);
    __shared__ float ws[8];
    if (lane == 0) ws[wid] = facc;
    __syncthreads();
    if (wid == 0) {
        float v = (lane < 8) ? ws[lane] : 0.0f;
        #pragma unroll
        for (int o = 4; o; o >>= 1) v += __shfl_xor_sync(0xffffffffu, v, o);
        if (lane == 0) atomicAdd(&g_acc[0], (double)v);
    }
}

__global__ void k_boundary(const float* __restrict__ V) {
    const int idx  = blockIdx.x * blockDim.x + threadIdx.x;   // 0..4095
    const int lane = threadIdx.x & 31;
    const int wid  = threadIdx.x >> 5;

    // far-field BC: row s = NS-1, t_j = j/4095
    float t  = (float)idx * INV4095;
    float vb = V[(size_t)(NS - 1) * ROWF + idx];
    float tgt = 1.0f - (100.0f / 300.0f) * expf(-0.05f * (1.0f - t));
    float db  = vb - tgt;
    float bc  = db * db;

    // terminal condition: col j = NT-1, softplus payoff + huber
    float u  = (float)idx * INV4095;
    float vt = V[(size_t)idx * ROWF + (NT - 1)];
    float x  = 50.0f * (u - (100.0f / 300.0f));
    float sp = fmaxf(x, 0.0f) + log1pf(expf(-fabsf(x)));
    float payoff = sp * 0.02f;
    float d  = vt - payoff;
    float ad = fabsf(d);
    float tc = (ad < 0.01f) ? 0.5f * d * d : 0.01f * (ad - 0.005f);

    #pragma unroll
    for (int o = 16; o; o >>= 1) {
        bc += __shfl_xor_sync(0xffffffffu, bc, o);
        tc += __shfl_xor_sync(0xffffffffu, tc, o);
    }
    __shared__ float wb[8], wt[8];
    if (lane == 0) { wb[wid] = bc; wt[wid] = tc; }
    __syncthreads();
    if (wid == 0) {
        float b = (lane < 8) ? wb[lane] : 0.0f;
        float c = (lane < 8) ? wt[lane] : 0.0f;
        #pragma unroll
        for (int o = 4; o; o >>= 1) {
            b += __shfl_xor_sync(0xffffffffu, b, o);
            c += __shfl_xor_sync(0xffffffffu, c, o);
        }
        if (lane == 0) {
            atomicAdd(&g_acc[1], (double)b);
            atomicAdd(&g_acc[2], (double)c);
        }
    }
}

__global__ void k_final(float* __restrict__ out) {
    const double n_int = (double)(NS - 2) * (double)(NT - 2);
    double total = g_acc[0] / n_int
                 + 10.0 * (g_acc[1] / (double)NT)
                 + 10.0 * (g_acc[2] / (double)NS);
    out[0] = (float)total;
}

// host-side cubic root (CubicStretching), double precision
static double solve_depressed_cubic(double Q) {
    const double p = 6.0;
    double q = 6.0 * Q;
    double sp = sqrt(p);
    double arg = fabs(q) / (2.0 * p * sp / (3.0 * sqrt(3.0)));
    if (arg < 1.0) arg = 1.0;
    double c = 2.0 * sp * cosh(acosh(arg) / 3.0);
    return (q >= 0.0) ? -c : c;
}

extern "C" void kernel_launch(void* const* d_in, const int* in_sizes, int n_in,
                              void* d_out, int out_size) {
    const float* V = (const float*)d_in[0];
    float* out = (float*)d_out;

    double C1 = solve_depressed_cubic((100.0 - 0.0)   / 30.0);
    double C2 = solve_depressed_cubic((100.0 - 300.0) / 30.0);

    k_zero<<<1, 1>>>();
    dim3 grid(4, 256);                 // 4 * 256 threads * 4 floats = 4096 cols; 256 strips of 16 rows
    k_pde<<<grid, 256>>>(V, (float)C1, (float)C2);
    k_boundary<<<16, 256>>>(V);
    k_final<<<1, 1>>>(out);
}